// round 3
// baseline (speedup 1.0000x reference)
#include <cuda_runtime.h>
#include <cstdint>
#include <cstddef>

// LSTM autoencoder, fused persistent kernel, round 3.
// 128 CTAs x 256 threads; each CTA owns 2 batch elements.
// Encoder: 1 barrier/step (L1[s] and L0[s+1] merged into one phase, shuffle-fused acts).
// Decoder: 2 barriers/step.
// Thread->gate map: lane = role*8 + jl, g = role*64 + warp*8 + jl.
// Act ownership: lane = al*16 + bb*8 + jl owns cellact for (layer al, batch bb, j).

#define Tn 1024

// smem float offsets
#define OFF_W1   0        // enc: [256][132] row g = [Wih1(64)|Whh1(64)]; dec: [256][68] Whh1
#define OFF_FC   33792    // [128][68] fc_W
#define OFF_FCB  42496    // [128]
#define OFF_X    42624    // [3][2][128] x slots
#define OFF_V    43392    // [2][2][128] parity, batch, (h0|h1)
#define SMEM_FLOATS 43904 // 175616 bytes

__device__ __align__(16) float g_M[256 * 64];   // dec_Wih0 @ fcW

__device__ __forceinline__ void fma2(unsigned long long& acc,
                                     unsigned long long a, unsigned long long b) {
    asm("fma.rn.f32x2 %0, %1, %2, %3;" : "=l"(acc) : "l"(a), "l"(b), "l"(acc));
}
__device__ __forceinline__ float psum(unsigned long long v) {
    float lo, hi;
    asm("mov.b64 {%0, %1}, %2;" : "=f"(lo), "=f"(hi) : "l"(v));
    return lo + hi;
}
__device__ __forceinline__ float sigm_f(float v) {
    return __fdividef(1.f, 1.f + __expf(-v));
}
__device__ __forceinline__ float tanh_f(float v) {
    float a = fabsf(v);
    float e = __expf(-2.f * a);
    float r = __fdividef(1.f - e, 1.f + e);
    return v < 0.f ? -r : r;
}
__device__ __forceinline__ float cellact(float gi, float gf, float gg, float go, float& c) {
    c = sigm_f(gf) * c + sigm_f(gi) * tanh_f(gg);
    return sigm_f(go) * tanh_f(c);
}

__global__ void prep_kernel(const float* __restrict__ dW0i, const float* __restrict__ fcW) {
    int id = blockIdx.x * blockDim.x + threadIdx.x;  // 0..16383
    int g = id >> 6, j = id & 63;
    float acc = 0.f;
    #pragma unroll 4
    for (int d = 0; d < 128; d++)
        acc = fmaf(dW0i[g * 128 + d], fcW[d * 64 + j], acc);
    g_M[id] = acc;
}

// gather the 4 role values for this lane's jl: src lane r*8+jl
#define GATHER4(dst, src) { \
    dst[0] = __shfl_sync(0xffffffffu, src, jl); \
    dst[1] = __shfl_sync(0xffffffffu, src, 8 + jl); \
    dst[2] = __shfl_sync(0xffffffffu, src, 16 + jl); \
    dst[3] = __shfl_sync(0xffffffffu, src, 24 + jl); }

__global__ void __launch_bounds__(256, 1)
lstm_ae_kernel(const float* __restrict__ x,
               const float* __restrict__ eW0i, const float* __restrict__ eW0h,
               const float* __restrict__ eb0i, const float* __restrict__ eb0h,
               const float* __restrict__ eW1i, const float* __restrict__ eW1h,
               const float* __restrict__ eb1i, const float* __restrict__ eb1h,
               const float* __restrict__ dW0i, const float* __restrict__ dW0h,
               const float* __restrict__ db0i, const float* __restrict__ db0h,
               const float* __restrict__ dW1i, const float* __restrict__ dW1h,
               const float* __restrict__ db1i, const float* __restrict__ db1h,
               const float* __restrict__ fcW,  const float* __restrict__ fcb,
               float* __restrict__ out)
{
    extern __shared__ float sm[];
    float* sW1  = sm + OFF_W1;
    float* sFC  = sm + OFF_FC;
    float* sFCb = sm + OFF_FCB;
    float* sX   = sm + OFF_X;
    float* sV   = sm + OFF_V;

    const int t    = threadIdx.x;
    const int b0   = blockIdx.x * 2;
    const int lane = t & 31, warp = t >> 5;
    const int jl   = lane & 7;
    const int role = lane >> 3;             // 0..3 (i,f,g,o)
    const int j    = warp * 8 + jl;         // 0..63
    const int g    = role * 64 + j;         // gate row 0..255 (permutation)
    const int al   = lane >> 4;             // act layer (0/1)
    const int ab2  = (lane >> 3) & 1;       // act batch (0/1)

    float cst = 0.f;                        // cell state for (al, ab2, j), this lane

    // ================= ENCODER =================
    {
        unsigned long long w0[96];   // [0..63]=Wih0[g] (128f), [64..95]=Whh0[g] (64f)
        {
            const ulonglong2* p = (const ulonglong2*)(eW0i + g * 128);
            #pragma unroll
            for (int i = 0; i < 32; i++) { ulonglong2 v = p[i]; w0[2*i] = v.x; w0[2*i+1] = v.y; }
            const ulonglong2* q = (const ulonglong2*)(eW0h + g * 64);
            #pragma unroll
            for (int i = 0; i < 16; i++) { ulonglong2 v = q[i]; w0[64+2*i] = v.x; w0[65+2*i] = v.y; }
        }
        float bias0 = eb0i[g] + eb0h[g];
        float bias1 = eb1i[g] + eb1h[g];
        for (int idx = t; idx < 256 * 64; idx += 256) {
            int r = idx >> 6, k = idx & 63;
            sW1[r * 132 + k]      = eW1i[idx];
            sW1[r * 132 + 64 + k] = eW1h[idx];
        }
        sV[t] = 0.f; sV[t + 256] = 0.f;      // both parity buffers

        // prefetch x[0..2] into slots 0..2
        #pragma unroll
        for (int s = 0; s < 3; s++) {
            if (t < 64) {
                int e = t >> 5, l32 = t & 31;
                const float* src = x + ((size_t)(b0 + e) * Tn + s) * 128 + l32 * 4;
                uint32_t dst = (uint32_t)__cvta_generic_to_shared(sX + (s * 2 + e) * 128 + l32 * 4);
                asm volatile("cp.async.cg.shared.global [%0], [%1], 16;" :: "r"(dst), "l"(src) : "memory");
            }
            asm volatile("cp.async.commit_group;" ::: "memory");
        }
        asm volatile("cp.async.wait_group 2;" ::: "memory");  // x[0] ready
        __syncthreads();

        // ---- prologue: L0 gates[0] (h=0 so x-part only) -> h0[0] into buffer 0 ----
        {
            unsigned long long a0 = 0, a1 = 0, b0q = 0, b1q = 0;
            const ulonglong2* x0p = (const ulonglong2*)(sX);
            const ulonglong2* x1p = (const ulonglong2*)(sX + 128);
            #pragma unroll
            for (int i = 0; i < 32; i++) {
                ulonglong2 va = x0p[i]; ulonglong2 vb = x1p[i];
                fma2(a0, w0[2*i], va.x); fma2(a1, w0[2*i+1], va.y);
                fma2(b0q, w0[2*i], vb.x); fma2(b1q, w0[2*i+1], vb.y);
            }
            float ga0 = psum(a0) + psum(a1) + bias0;
            float gb0 = psum(b0q) + psum(b1q) + bias0;
            float A[4], Bv[4];
            GATHER4(A, ga0); GATHER4(Bv, gb0);
            if (al == 0) {
                float gi = ab2 ? Bv[0] : A[0], gf = ab2 ? Bv[1] : A[1];
                float gg = ab2 ? Bv[2] : A[2], go = ab2 ? Bv[3] : A[3];
                sV[ab2 * 128 + j] = cellact(gi, gf, gg, go, cst);
            }
        }
        asm volatile("cp.async.wait_group 1;" ::: "memory");  // x[1] ready
        __syncthreads();

        // ---- main loop: phase s computes L1[s] + L0[s+1], acts, 1 barrier ----
        const ulonglong2* wrow = (const ulonglong2*)(sW1 + g * 132);
        for (int s = 0; s < Tn; s++) {
            const float* vR = sV + (s & 1) * 256;
            float*       vW = sV + ((s & 1) ^ 1) * 256;
            const bool doL0 = (s + 1) < Tn;

            // L1 gates[s]: concat [h0[s]|h1[s-1]] (128f) x sW1 row g
            float ga1, gb1;
            {
                const ulonglong2* v0 = (const ulonglong2*)(vR);
                const ulonglong2* v1 = (const ulonglong2*)(vR + 128);
                unsigned long long q00 = 0, q01 = 0, q10 = 0, q11 = 0;
                #pragma unroll
                for (int i = 0; i < 32; i++) {
                    ulonglong2 w = wrow[i]; ulonglong2 va = v0[i]; ulonglong2 vb = v1[i];
                    fma2(q00, w.x, va.x); fma2(q01, w.y, va.y);
                    fma2(q10, w.x, vb.x); fma2(q11, w.y, vb.y);
                }
                ga1 = psum(q00) + psum(q01) + bias1;
                gb1 = psum(q10) + psum(q11) + bias1;
            }

            // L0 gates[s+1]: x[s+1] (slot (s+1)%3) + h0[s]
            float ga0 = 0.f, gb0 = 0.f;
            if (doL0) {
                const float* xs = sX + ((s + 1) % 3) * 256;
                const ulonglong2* x0p = (const ulonglong2*)(xs);
                const ulonglong2* x1p = (const ulonglong2*)(xs + 128);
                unsigned long long a0 = 0, a1 = 0, b0q = 0, b1q = 0;
                #pragma unroll
                for (int i = 0; i < 32; i++) {
                    ulonglong2 va = x0p[i]; ulonglong2 vb = x1p[i];
                    fma2(a0, w0[2*i], va.x); fma2(a1, w0[2*i+1], va.y);
                    fma2(b0q, w0[2*i], vb.x); fma2(b1q, w0[2*i+1], vb.y);
                }
                const ulonglong2* h0a = (const ulonglong2*)(vR);
                const ulonglong2* h0b = (const ulonglong2*)(vR + 128);
                #pragma unroll
                for (int i = 0; i < 16; i++) {
                    ulonglong2 va = h0a[i]; ulonglong2 vb = h0b[i];
                    fma2(a0, w0[64+2*i], va.x); fma2(a1, w0[65+2*i], va.y);
                    fma2(b0q, w0[64+2*i], vb.x); fma2(b1q, w0[65+2*i], vb.y);
                }
                ga0 = psum(a0) + psum(a1) + bias0;
                gb0 = psum(b0q) + psum(b1q) + bias0;
            }

            // prefetch x[s+3] into slot s%3
            if (t < 64 && s + 3 < Tn) {
                int e = t >> 5, l32 = t & 31;
                const float* src = x + ((size_t)(b0 + e) * Tn + (s + 3)) * 128 + l32 * 4;
                uint32_t dst = (uint32_t)__cvta_generic_to_shared(sX + ((s % 3) * 2 + e) * 128 + l32 * 4);
                asm volatile("cp.async.cg.shared.global [%0], [%1], 16;" :: "r"(dst), "l"(src) : "memory");
                asm volatile("cp.async.commit_group;" ::: "memory");
            }

            // shuffle-fused acts
            {
                float C[4], D[4];
                GATHER4(C, ga1); GATHER4(D, gb1);
                float A[4], Bv[4];
                if (doL0) { GATHER4(A, ga0); GATHER4(Bv, gb0); }
                if (al == 1) {   // act1[s] -> h1[s]
                    float gi = ab2 ? D[0] : C[0], gf = ab2 ? D[1] : C[1];
                    float gg = ab2 ? D[2] : C[2], go = ab2 ? D[3] : C[3];
                    vW[ab2 * 128 + 64 + j] = cellact(gi, gf, gg, go, cst);
                } else if (doL0) { // act0[s+1] -> h0[s+1]
                    float gi = ab2 ? Bv[0] : A[0], gf = ab2 ? Bv[1] : A[1];
                    float gg = ab2 ? Bv[2] : A[2], go = ab2 ? Bv[3] : A[3];
                    vW[ab2 * 128 + j] = cellact(gi, gf, gg, go, cst);
                }
            }
            asm volatile("cp.async.wait_group 1;" ::: "memory");
            __syncthreads();
        }
    }

    // ================= TRANSITION =================
    // final: h0[T-1] in buffer 1, h1[T-1] in buffer 0. Build decoder state in buffer 0.
    {
        cst = tanh_f(cst);
        float hv = (al == 0) ? sV[256 + ab2 * 128 + j]      // h0 from buffer 1
                             : sV[ab2 * 128 + 64 + j];      // h1 from buffer 0
        hv = tanh_f(hv);
        __syncthreads();   // all reads done before h0-region overwrite
        sV[ab2 * 128 + al * 64 + j] = hv;                   // into buffer 0
    }
    unsigned long long wA[64];  // [0..31]=Whh0[g] (64f over h0), [32..63]=M[g] (64f over h1)
    unsigned long long wC[32];  // Wih1[g] (64f over h0)
    {
        const ulonglong2* p = (const ulonglong2*)(dW0h + g * 64);
        #pragma unroll
        for (int i = 0; i < 16; i++) { ulonglong2 v = p[i]; wA[2*i] = v.x; wA[2*i+1] = v.y; }
        const ulonglong2* q = (const ulonglong2*)(g_M + g * 64);
        #pragma unroll
        for (int i = 0; i < 16; i++) { ulonglong2 v = q[i]; wA[32+2*i] = v.x; wA[33+2*i] = v.y; }
        const ulonglong2* r = (const ulonglong2*)(dW1i + g * 64);
        #pragma unroll
        for (int i = 0; i < 16; i++) { ulonglong2 v = r[i]; wC[2*i] = v.x; wC[2*i+1] = v.y; }
    }
    float bias0 = db0i[g] + db0h[g];
    float b0fold;
    {
        float a = 0.f;
        #pragma unroll 4
        for (int d = 0; d < 128; d++) a = fmaf(dW0i[g * 128 + d], fcb[d], a);
        b0fold = bias0 + a;
    }
    float bias1 = db1i[g] + db1h[g];
    for (int idx = t; idx < 256 * 64; idx += 256) {
        int r = idx >> 6, k = idx & 63;
        sW1[r * 68 + k] = dW1h[idx];
    }
    for (int idx = t; idx < 128 * 64; idx += 256) {
        int o = idx >> 6, k = idx & 63;
        sFC[o * 68 + k] = fcW[idx];
    }
    if (t < 128) sFCb[t] = fcb[t];
    __syncthreads();

    // ================= DECODER =================
    const int oF = t & 127, bF = t >> 7;               // FC task
    const ulonglong2* whh1 = (const ulonglong2*)(sW1 + g * 68);
    const ulonglong2* wfc  = (const ulonglong2*)(sFC + oF * 68);
    const float fcbO = sFCb[oF];

    for (int s = 0; s < Tn; s++) {
        const float* vR = sV + (s & 1) * 256;
        float*       vW = sV + ((s & 1) ^ 1) * 256;
        const bool first = (s == 0);

        // ---- ph1: gates0[s] + p(Whh1) + deferred FC -> act0 ----
        float p0, p1;
        {
            // gates0 = Whh0*h0[s-1] (+ M*h1[s-1] if s>0)
            const ulonglong2* h0a = (const ulonglong2*)(vR);
            const ulonglong2* h0b = (const ulonglong2*)(vR + 128);
            unsigned long long a0 = 0, a1 = 0, c0q = 0, c1q = 0;
            #pragma unroll
            for (int i = 0; i < 16; i++) {
                ulonglong2 va = h0a[i]; ulonglong2 vb = h0b[i];
                fma2(a0, wA[2*i], va.x); fma2(a1, wA[2*i+1], va.y);
                fma2(c0q, wA[2*i], vb.x); fma2(c1q, wA[2*i+1], vb.y);
            }
            float ga0, gb0;
            const ulonglong2* h1a = (const ulonglong2*)(vR + 64);
            const ulonglong2* h1b = (const ulonglong2*)(vR + 192);
            if (!first) {
                #pragma unroll
                for (int i = 0; i < 16; i++) {
                    ulonglong2 va = h1a[i]; ulonglong2 vb = h1b[i];
                    fma2(a0, wA[32+2*i], va.x); fma2(a1, wA[33+2*i], va.y);
                    fma2(c0q, wA[32+2*i], vb.x); fma2(c1q, wA[33+2*i], vb.y);
                }
                ga0 = psum(a0) + psum(a1) + b0fold;
                gb0 = psum(c0q) + psum(c1q) + b0fold;
            } else {
                ga0 = psum(a0) + psum(a1) + bias0;
                gb0 = psum(c0q) + psum(c1q) + bias0;
            }

            // p = h1[s-1] @ Whh1 + bias1 (both batches), carried to ph2 in regs
            {
                unsigned long long q00 = 0, q01 = 0, q10 = 0, q11 = 0;
                #pragma unroll
                for (int i = 0; i < 16; i++) {
                    ulonglong2 w = whh1[i]; ulonglong2 va = h1a[i]; ulonglong2 vb = h1b[i];
                    fma2(q00, w.x, va.x); fma2(q01, w.y, va.y);
                    fma2(q10, w.x, vb.x); fma2(q11, w.y, vb.y);
                }
                p0 = psum(q00) + psum(q01) + bias1;
                p1 = psum(q10) + psum(q11) + bias1;
            }

            // deferred FC of h1[s-1] -> out[s-1]
            if (!first) {
                const ulonglong2* hp = (const ulonglong2*)(vR + bF * 128 + 64);
                unsigned long long f0 = 0, f1 = 0;
                #pragma unroll
                for (int i = 0; i < 16; i++) {
                    ulonglong2 w = wfc[i]; ulonglong2 h = hp[i];
                    fma2(f0, w.x, h.x); fma2(f1, w.y, h.y);
                }
                out[((size_t)(b0 + bF) * Tn + (s - 1)) * 128 + oF] = psum(f0) + psum(f1) + fcbO;
            }

            // act0 -> h0[s]
            float A[4], Bv[4];
            GATHER4(A, ga0); GATHER4(Bv, gb0);
            if (al == 0) {
                float gi = ab2 ? Bv[0] : A[0], gf = ab2 ? Bv[1] : A[1];
                float gg = ab2 ? Bv[2] : A[2], go = ab2 ? Bv[3] : A[3];
                vW[ab2 * 128 + j] = cellact(gi, gf, gg, go, cst);
            }
        }
        __syncthreads();

        // ---- ph2: gates1[s] = h0[s]@Wih1 + p -> act1 ----
        {
            const ulonglong2* h0a = (const ulonglong2*)(vW);
            const ulonglong2* h0b = (const ulonglong2*)(vW + 128);
            unsigned long long q00 = 0, q01 = 0, q10 = 0, q11 = 0;
            #pragma unroll
            for (int i = 0; i < 16; i++) {
                ulonglong2 va = h0a[i]; ulonglong2 vb = h0b[i];
                fma2(q00, wC[2*i], va.x); fma2(q01, wC[2*i+1], va.y);
                fma2(q10, wC[2*i], vb.x); fma2(q11, wC[2*i+1], vb.y);
            }
            float ga1 = psum(q00) + psum(q01) + p0;
            float gb1 = psum(q10) + psum(q11) + p1;

            float C[4], D[4];
            GATHER4(C, ga1); GATHER4(D, gb1);
            if (al == 1) {
                float gi = ab2 ? D[0] : C[0], gf = ab2 ? D[1] : C[1];
                float gg = ab2 ? D[2] : C[2], go = ab2 ? D[3] : C[3];
                vW[ab2 * 128 + 64 + j] = cellact(gi, gf, gg, go, cst);
            }
        }
        __syncthreads();
    }

    // final FC for h1[T-1] (in buffer 0)
    {
        const ulonglong2* hp = (const ulonglong2*)(sV + bF * 128 + 64);
        unsigned long long f0 = 0, f1 = 0;
        #pragma unroll
        for (int i = 0; i < 16; i++) {
            ulonglong2 w = wfc[i]; ulonglong2 h = hp[i];
            fma2(f0, w.x, h.x); fma2(f1, w.y, h.y);
        }
        out[((size_t)(b0 + bF) * Tn + (Tn - 1)) * 128 + oF] = psum(f0) + psum(f1) + fcbO;
    }
}

extern "C" void kernel_launch(void* const* d_in, const int* in_sizes, int n_in,
                              void* d_out, int out_size) {
    (void)in_sizes; (void)n_in; (void)out_size;
    const float* x    = (const float*)d_in[0];
    const float* eW0i = (const float*)d_in[1];
    const float* eW0h = (const float*)d_in[2];
    const float* eb0i = (const float*)d_in[3];
    const float* eb0h = (const float*)d_in[4];
    const float* eW1i = (const float*)d_in[5];
    const float* eW1h = (const float*)d_in[6];
    const float* eb1i = (const float*)d_in[7];
    const float* eb1h = (const float*)d_in[8];
    const float* dW0i = (const float*)d_in[9];
    const float* dW0h = (const float*)d_in[10];
    const float* db0i = (const float*)d_in[11];
    const float* db0h = (const float*)d_in[12];
    const float* dW1i = (const float*)d_in[13];
    const float* dW1h = (const float*)d_in[14];
    const float* db1i = (const float*)d_in[15];
    const float* db1h = (const float*)d_in[16];
    const float* fcW  = (const float*)d_in[17];
    const float* fcb  = (const float*)d_in[18];

    prep_kernel<<<64, 256>>>(dW0i, fcW);

    cudaFuncSetAttribute(lstm_ae_kernel, cudaFuncAttributeMaxDynamicSharedMemorySize,
                         SMEM_FLOATS * (int)sizeof(float));
    lstm_ae_kernel<<<128, 256, SMEM_FLOATS * sizeof(float)>>>(
        x, eW0i, eW0h, eb0i, eb0h, eW1i, eW1h, eb1i, eb1h,
        dW0i, dW0h, db0i, db0h, dW1i, dW1h, db1i, db1h,
        fcW, fcb, (float*)d_out);
}

// round 4
// speedup vs baseline: 1.6349x; 1.6349x over previous
#include <cuda_runtime.h>
#include <cstdint>
#include <cstddef>

// LSTM autoencoder, fused persistent kernel, round 4 = round 2 + conflict-free
// chunk-interleaved smem weight layouts.
// 128 CTAs x 256 threads; each CTA owns 2 batch elements.
//
// Weight layout in smem: chunk c (4 consecutive k's) of gate g at float offset
// c*1024 + g*4  (FC: c*512 + o*4). Lane t loads ulonglong2 [c*256 + t]:
// 32 lanes -> 512 contiguous bytes -> conflict-free LDS.128.

#define Tn 1024

// smem float offsets
#define OFF_WA   0        // enc: Wih1 blocked [16 chunks][256 g][4]; dec: Whh1 blocked
#define OFF_WB   16384    // enc: Whh1 blocked; dec: FC blocked (8192) + fcb @ +8192
#define OFF_X    32768    // [2][2][128] x double-buffer
#define OFF_V    33280    // [2][128] per-batch [h0(64)|h1(64)]
#define OFF_G    33536    // [2][256] gate scratch
#define SMEM_FLOATS 34048 // 136192 bytes

__device__ __align__(16) float g_M[256 * 64];   // dec_Wih0 @ fcW

__device__ __forceinline__ void fma2(unsigned long long& acc,
                                     unsigned long long a, unsigned long long b) {
    asm("fma.rn.f32x2 %0, %1, %2, %3;" : "=l"(acc) : "l"(a), "l"(b), "l"(acc));
}
__device__ __forceinline__ float psum(unsigned long long v) {
    float lo, hi;
    asm("mov.b64 {%0, %1}, %2;" : "=f"(lo), "=f"(hi) : "l"(v));
    return lo + hi;
}
__device__ __forceinline__ float sigm_f(float v) {
    return __fdividef(1.f, 1.f + __expf(-v));
}
__device__ __forceinline__ float tanh_f(float v) {
    float a = fabsf(v);
    float e = __expf(-2.f * a);
    float r = __fdividef(1.f - e, 1.f + e);
    return v < 0.f ? -r : r;
}
__device__ __forceinline__ float cellact(float gi, float gf, float gg, float go, float& c) {
    c = sigm_f(gf) * c + sigm_f(gi) * tanh_f(gg);
    return sigm_f(go) * tanh_f(c);
}

// encoder L0 preactivation: 128-elem x-part + 64-elem h-part, weights in regs
__device__ __forceinline__ float dot192(const unsigned long long (&w)[96],
                                        const float* xs, const float* hs, float bias) {
    unsigned long long a0 = 0ull, a1 = 0ull;
    const ulonglong2* xp = (const ulonglong2*)xs;
    #pragma unroll
    for (int i = 0; i < 32; i++) {
        ulonglong2 v = xp[i];
        fma2(a0, w[2 * i], v.x);
        fma2(a1, w[2 * i + 1], v.y);
    }
    const ulonglong2* hp = (const ulonglong2*)hs;
    #pragma unroll
    for (int i = 0; i < 16; i++) {
        ulonglong2 v = hp[i];
        fma2(a0, w[64 + 2 * i], v.x);
        fma2(a1, w[65 + 2 * i], v.y);
    }
    return psum(a0) + psum(a1) + bias;
}

__global__ void prep_kernel(const float* __restrict__ dW0i, const float* __restrict__ fcW) {
    int id = blockIdx.x * blockDim.x + threadIdx.x;  // 0..16383
    int g = id >> 6, j = id & 63;
    float acc = 0.f;
    #pragma unroll 4
    for (int d = 0; d < 128; d++)
        acc = fmaf(dW0i[g * 128 + d], fcW[d * 64 + j], acc);
    g_M[id] = acc;
}

__global__ void __launch_bounds__(256, 1)
lstm_ae_kernel(const float* __restrict__ x,
               const float* __restrict__ eW0i, const float* __restrict__ eW0h,
               const float* __restrict__ eb0i, const float* __restrict__ eb0h,
               const float* __restrict__ eW1i, const float* __restrict__ eW1h,
               const float* __restrict__ eb1i, const float* __restrict__ eb1h,
               const float* __restrict__ dW0i, const float* __restrict__ dW0h,
               const float* __restrict__ db0i, const float* __restrict__ db0h,
               const float* __restrict__ dW1i, const float* __restrict__ dW1h,
               const float* __restrict__ db1i, const float* __restrict__ db1h,
               const float* __restrict__ fcW,  const float* __restrict__ fcb,
               float* __restrict__ out)
{
    extern __shared__ float sm[];
    float* sWA  = sm + OFF_WA;
    float* sWB  = sm + OFF_WB;
    float* sFC  = sm + OFF_WB;            // decoder: FC blocked lives in WB
    float* sFCb = sm + OFF_WB + 8192;
    float* sX   = sm + OFF_X;
    float* sV   = sm + OFF_V;
    float* sG   = sm + OFF_G;

    const int t  = threadIdx.x;
    const int b0 = blockIdx.x * 2;
    const int aj = t & 63;
    const int ab = (t >> 6) & 1;

    float c0 = 0.f, c1 = 0.f;

    // ================= ENCODER =================
    {
        unsigned long long w0[96];   // Wih0 row t (128 fl) | Whh0 row t (64 fl)
        {
            const ulonglong2* p = (const ulonglong2*)(eW0i + t * 128);
            #pragma unroll
            for (int i = 0; i < 32; i++) { ulonglong2 v = p[i]; w0[2*i] = v.x; w0[2*i+1] = v.y; }
            const ulonglong2* q = (const ulonglong2*)(eW0h + t * 64);
            #pragma unroll
            for (int i = 0; i < 16; i++) { ulonglong2 v = q[i]; w0[64+2*i] = v.x; w0[65+2*i] = v.y; }
        }
        float bias0 = eb0i[t] + eb0h[t];
        float bias1 = eb1i[t] + eb1h[t];
        // blocked staging: chunk c of gate g at c*1024 + g*4
        for (int idx = t; idx < 256 * 64; idx += 256) {
            int g = idx >> 6, k = idx & 63;
            int c = k >> 2, m = k & 3;
            sWA[c * 1024 + g * 4 + m] = eW1i[idx];
            sWB[c * 1024 + g * 4 + m] = eW1h[idx];
        }
        sV[t] = 0.f;

        // prefetch x steps 0,1
        #pragma unroll
        for (int s = 0; s < 2; s++) {
            if (t < 64) {
                int e = t >> 5, lane = t & 31;
                const float* src = x + ((size_t)(b0 + e) * Tn + s) * 128 + lane * 4;
                uint32_t dst = (uint32_t)__cvta_generic_to_shared(sX + (s * 2 + e) * 128 + lane * 4);
                asm volatile("cp.async.cg.shared.global [%0], [%1], 16;" :: "r"(dst), "l"(src) : "memory");
            }
            asm volatile("cp.async.commit_group;" ::: "memory");
        }
        asm volatile("cp.async.wait_group 1;" ::: "memory");
        __syncthreads();

        const ulonglong2* wip = (const ulonglong2*)sWA;   // [c*256 + t]
        const ulonglong2* whp = (const ulonglong2*)sWB;

        for (int step = 0; step < Tn; step++) {
            // P1: L0 gates + h1part (h1_prev @ Whh1)
            float p0, p1;
            {
                const float* xs0 = sX + ((step & 1) * 2) * 128;
                float ga = dot192(w0, xs0,       sV,       bias0);
                float gb = dot192(w0, xs0 + 128, sV + 128, bias0);
                const ulonglong2* h1a = (const ulonglong2*)(sV + 64);
                const ulonglong2* h1b = (const ulonglong2*)(sV + 192);
                unsigned long long q00 = 0, q01 = 0, q10 = 0, q11 = 0;
                #pragma unroll
                for (int i = 0; i < 8; i++) {
                    ulonglong2 w0c = whp[(2*i) * 256 + t];
                    ulonglong2 w1c = whp[(2*i+1) * 256 + t];
                    ulonglong2 va0 = h1a[2*i], va1 = h1a[2*i+1];
                    ulonglong2 vb0 = h1b[2*i], vb1 = h1b[2*i+1];
                    fma2(q00, w0c.x, va0.x); fma2(q01, w0c.y, va0.y);
                    fma2(q10, w0c.x, vb0.x); fma2(q11, w0c.y, vb0.y);
                    fma2(q00, w1c.x, va1.x); fma2(q01, w1c.y, va1.y);
                    fma2(q10, w1c.x, vb1.x); fma2(q11, w1c.y, vb1.y);
                }
                p0 = psum(q00) + psum(q01);
                p1 = psum(q10) + psum(q11);
                sG[t] = ga; sG[256 + t] = gb;
            }
            __syncthreads();

            // P2: act0 + prefetch step+2
            if (t < 128) {
                const float* g = sG + ab * 256;
                sV[ab * 128 + aj] = cellact(g[aj], g[64 + aj], g[128 + aj], g[192 + aj], c0);
            }
            if (t < 64 && step + 2 < Tn) {
                int e = t >> 5, lane = t & 31;
                const float* src = x + ((size_t)(b0 + e) * Tn + (step + 2)) * 128 + lane * 4;
                uint32_t dst = (uint32_t)__cvta_generic_to_shared(sX + ((step & 1) * 2 + e) * 128 + lane * 4);
                asm volatile("cp.async.cg.shared.global [%0], [%1], 16;" :: "r"(dst), "l"(src) : "memory");
            }
            asm volatile("cp.async.commit_group;" ::: "memory");
            __syncthreads();

            // P3: L1 gates = h0 @ Wih1 + h1part
            {
                const ulonglong2* h0a = (const ulonglong2*)(sV);
                const ulonglong2* h0b = (const ulonglong2*)(sV + 128);
                unsigned long long q00 = 0, q01 = 0, q10 = 0, q11 = 0;
                #pragma unroll
                for (int i = 0; i < 8; i++) {
                    ulonglong2 w0c = wip[(2*i) * 256 + t];
                    ulonglong2 w1c = wip[(2*i+1) * 256 + t];
                    ulonglong2 va0 = h0a[2*i], va1 = h0a[2*i+1];
                    ulonglong2 vb0 = h0b[2*i], vb1 = h0b[2*i+1];
                    fma2(q00, w0c.x, va0.x); fma2(q01, w0c.y, va0.y);
                    fma2(q10, w0c.x, vb0.x); fma2(q11, w0c.y, vb0.y);
                    fma2(q00, w1c.x, va1.x); fma2(q01, w1c.y, va1.y);
                    fma2(q10, w1c.x, vb1.x); fma2(q11, w1c.y, vb1.y);
                }
                sG[t]       = psum(q00) + psum(q01) + p0 + bias1;
                sG[256 + t] = psum(q10) + psum(q11) + p1 + bias1;
            }
            __syncthreads();

            // P4: act1
            if (t < 128) {
                const float* g = sG + ab * 256;
                sV[ab * 128 + 64 + aj] = cellact(g[aj], g[64 + aj], g[128 + aj], g[192 + aj], c1);
            }
            asm volatile("cp.async.wait_group 1;" ::: "memory");
            __syncthreads();
        }
        asm volatile("cp.async.wait_group 0;" ::: "memory");
    }

    // ================= TRANSITION =================
    if (t < 128) {
        c0 = tanh_f(c0);
        c1 = tanh_f(c1);
        sV[ab * 128 + aj]      = tanh_f(sV[ab * 128 + aj]);
        sV[ab * 128 + 64 + aj] = tanh_f(sV[ab * 128 + 64 + aj]);
    }
    unsigned long long wA[64];  // [0..31] M row (over h1), [32..63] Whh0 row (over h0)
    unsigned long long wC[32];  // Wih1 row (over h0)
    {
        const ulonglong2* p = (const ulonglong2*)(g_M + t * 64);
        #pragma unroll
        for (int i = 0; i < 16; i++) { ulonglong2 v = p[i]; wA[2*i] = v.x; wA[2*i+1] = v.y; }
        const ulonglong2* q = (const ulonglong2*)(dW0h + t * 64);
        #pragma unroll
        for (int i = 0; i < 16; i++) { ulonglong2 v = q[i]; wA[32+2*i] = v.x; wA[33+2*i] = v.y; }
        const ulonglong2* r = (const ulonglong2*)(dW1i + t * 64);
        #pragma unroll
        for (int i = 0; i < 16; i++) { ulonglong2 v = r[i]; wC[2*i] = v.x; wC[2*i+1] = v.y; }
    }
    float bias0 = db0i[t] + db0h[t];
    float b0fold;
    {
        float a = 0.f;
        #pragma unroll 4
        for (int d = 0; d < 128; d++) a = fmaf(dW0i[t * 128 + d], fcb[d], a);
        b0fold = bias0 + a;   // bias0 + Wih0 @ fcb
    }
    float bias1 = db1i[t] + db1h[t];
    __syncthreads();   // encoder reads of sWA/sWB done before overwrite
    // dec Whh1 blocked into WA; FC blocked into WB
    for (int idx = t; idx < 256 * 64; idx += 256) {
        int g = idx >> 6, k = idx & 63;
        int c = k >> 2, m = k & 3;
        sWA[c * 1024 + g * 4 + m] = dW1h[idx];
    }
    for (int idx = t; idx < 128 * 64; idx += 256) {
        int o = idx >> 6, k = idx & 63;
        int c = k >> 2, m = k & 3;
        sFC[c * 512 + o * 4 + m] = fcW[idx];
    }
    if (t < 128) sFCb[t] = fcb[t];
    __syncthreads();

    // ================= DECODER =================
    const int oF = t & 127, bF = t >> 7;
    const ulonglong2* whp = (const ulonglong2*)sWA;   // [c*256 + t]
    const ulonglong2* wfc = (const ulonglong2*)sFC;   // [c*128 + oF]
    const float fcbO = sFCb[oF];

    for (int step = 0; step < Tn; step++) {
        // P1: gates0 = Whh0*h0_prev (+ M*h1_prev if step>0) + deferred FC -> out[step-1]
        {
            const ulonglong2* h0a = (const ulonglong2*)(sV);
            const ulonglong2* h0b = (const ulonglong2*)(sV + 128);
            const ulonglong2* h1a = (const ulonglong2*)(sV + 64);
            const ulonglong2* h1b = (const ulonglong2*)(sV + 192);
            unsigned long long a0 = 0, a1 = 0, c0q = 0, c1q = 0;
            #pragma unroll
            for (int i = 0; i < 16; i++) {
                ulonglong2 va = h0a[i]; ulonglong2 vb = h0b[i];
                fma2(a0, wA[32 + 2*i], va.x); fma2(a1, wA[33 + 2*i], va.y);
                fma2(c0q, wA[32 + 2*i], vb.x); fma2(c1q, wA[33 + 2*i], vb.y);
            }
            float ga, gb;
            if (step > 0) {
                #pragma unroll
                for (int i = 0; i < 16; i++) {
                    ulonglong2 va = h1a[i]; ulonglong2 vb = h1b[i];
                    fma2(a0, wA[2*i], va.x); fma2(a1, wA[2*i+1], va.y);
                    fma2(c0q, wA[2*i], vb.x); fma2(c1q, wA[2*i+1], vb.y);
                }
                ga = psum(a0) + psum(a1) + b0fold;
                gb = psum(c0q) + psum(c1q) + b0fold;
                // deferred FC of previous h1
                const ulonglong2* hp = (const ulonglong2*)(sV + bF * 128 + 64);
                unsigned long long f0 = 0, f1 = 0;
                #pragma unroll
                for (int i = 0; i < 8; i++) {
                    ulonglong2 wc0 = wfc[(2*i) * 128 + oF];
                    ulonglong2 wc1 = wfc[(2*i+1) * 128 + oF];
                    ulonglong2 h0v = hp[2*i], h1v = hp[2*i+1];
                    fma2(f0, wc0.x, h0v.x); fma2(f1, wc0.y, h0v.y);
                    fma2(f0, wc1.x, h1v.x); fma2(f1, wc1.y, h1v.y);
                }
                float pr = psum(f0) + psum(f1) + fcbO;
                out[((size_t)(b0 + bF) * Tn + (step - 1)) * 128 + oF] = pr;
            } else {
                ga = psum(a0) + psum(a1) + bias0;
                gb = psum(c0q) + psum(c1q) + bias0;
            }
            sG[t] = ga; sG[256 + t] = gb;
        }
        __syncthreads();

        // P2: act0 + h1part (h1_prev @ Whh1, blocked smem)
        float p0, p1;
        {
            const ulonglong2* h1a = (const ulonglong2*)(sV + 64);
            const ulonglong2* h1b = (const ulonglong2*)(sV + 192);
            unsigned long long q00 = 0, q01 = 0, q10 = 0, q11 = 0;
            #pragma unroll
            for (int i = 0; i < 8; i++) {
                ulonglong2 w0c = whp[(2*i) * 256 + t];
                ulonglong2 w1c = whp[(2*i+1) * 256 + t];
                ulonglong2 va0 = h1a[2*i], va1 = h1a[2*i+1];
                ulonglong2 vb0 = h1b[2*i], vb1 = h1b[2*i+1];
                fma2(q00, w0c.x, va0.x); fma2(q01, w0c.y, va0.y);
                fma2(q10, w0c.x, vb0.x); fma2(q11, w0c.y, vb0.y);
                fma2(q00, w1c.x, va1.x); fma2(q01, w1c.y, va1.y);
                fma2(q10, w1c.x, vb1.x); fma2(q11, w1c.y, vb1.y);
            }
            p0 = psum(q00) + psum(q01);
            p1 = psum(q10) + psum(q11);
        }
        if (t < 128) {
            const float* g = sG + ab * 256;
            sV[ab * 128 + aj] = cellact(g[aj], g[64 + aj], g[128 + aj], g[192 + aj], c0);
        }
        __syncthreads();

        // P3: L1 gates = h0 @ Wih1 (regs) + h1part
        {
            const ulonglong2* h0a = (const ulonglong2*)(sV);
            const ulonglong2* h0b = (const ulonglong2*)(sV + 128);
            unsigned long long q00 = 0, q01 = 0, q10 = 0, q11 = 0;
            #pragma unroll
            for (int i = 0; i < 16; i++) {
                ulonglong2 va = h0a[i]; ulonglong2 vb = h0b[i];
                fma2(q00, wC[2*i], va.x); fma2(q01, wC[2*i+1], va.y);
                fma2(q10, wC[2*i], vb.x); fma2(q11, wC[2*i+1], vb.y);
            }
            sG[t]       = psum(q00) + psum(q01) + p0 + bias1;
            sG[256 + t] = psum(q10) + psum(q11) + p1 + bias1;
        }
        __syncthreads();

        // P4: act1
        if (t < 128) {
            const float* g = sG + ab * 256;
            sV[ab * 128 + 64 + aj] = cellact(g[aj], g[64 + aj], g[128 + aj], g[192 + aj], c1);
        }
        __syncthreads();
    }

    // final FC for last step's h1
    {
        const ulonglong2* hp = (const ulonglong2*)(sV + bF * 128 + 64);
        unsigned long long f0 = 0, f1 = 0;
        #pragma unroll
        for (int i = 0; i < 8; i++) {
            ulonglong2 wc0 = wfc[(2*i) * 128 + oF];
            ulonglong2 wc1 = wfc[(2*i+1) * 128 + oF];
            ulonglong2 h0v = hp[2*i], h1v = hp[2*i+1];
            fma2(f0, wc0.x, h0v.x); fma2(f1, wc0.y, h0v.y);
            fma2(f0, wc1.x, h1v.x); fma2(f1, wc1.y, h1v.y);
        }
        float pr = psum(f0) + psum(f1) + fcbO;
        out[((size_t)(b0 + bF) * Tn + (Tn - 1)) * 128 + oF] = pr;
    }
}

extern "C" void kernel_launch(void* const* d_in, const int* in_sizes, int n_in,
                              void* d_out, int out_size) {
    (void)in_sizes; (void)n_in; (void)out_size;
    const float* x    = (const float*)d_in[0];
    const float* eW0i = (const float*)d_in[1];
    const float* eW0h = (const float*)d_in[2];
    const float* eb0i = (const float*)d_in[3];
    const float* eb0h = (const float*)d_in[4];
    const float* eW1i = (const float*)d_in[5];
    const float* eW1h = (const float*)d_in[6];
    const float* eb1i = (const float*)d_in[7];
    const float* eb1h = (const float*)d_in[8];
    const float* dW0i = (const float*)d_in[9];
    const float* dW0h = (const float*)d_in[10];
    const float* db0i = (const float*)d_in[11];
    const float* db0h = (const float*)d_in[12];
    const float* dW1i = (const float*)d_in[13];
    const float* dW1h = (const float*)d_in[14];
    const float* db1i = (const float*)d_in[15];
    const float* db1h = (const float*)d_in[16];
    const float* fcW  = (const float*)d_in[17];
    const float* fcb  = (const float*)d_in[18];

    prep_kernel<<<64, 256>>>(dW0i, fcW);

    cudaFuncSetAttribute(lstm_ae_kernel, cudaFuncAttributeMaxDynamicSharedMemorySize,
                         SMEM_FLOATS * (int)sizeof(float));
    lstm_ae_kernel<<<128, 256, SMEM_FLOATS * sizeof(float)>>>(
        x, eW0i, eW0h, eb0i, eb0h, eW1i, eW1h, eb1i, eb1h,
        dW0i, dW0h, db0i, db0h, dW1i, dW1h, db1i, db1h,
        fcW, fcb, (float*)d_out);
}